// round 14
// baseline (speedup 1.0000x reference)
#include <cuda_runtime.h>
#include <math_constants.h>

#define NBOX   10647          // 52*52*3 + 26*26*3 + 13*13*3
#define NBATCH 4
#define DET_ELEMS (NBATCH*NBOX*6)
#define CAP    256            // per-(batch,class) bucket capacity (mean ~66, >20 sigma safe)

#define QTOT    845           // float4-quads over scale1+scale2 spatial (676 + 169)
#define NQT     (3*NBATCH*QTOT)              // 10140 quad-teams
#define QTHREADS (NQT*4)                     // 40560 quad lanes
#define QEND    (((QTHREADS)+31) & ~31)      // 40576: pad to warp boundary
#define S3THREADS (3*NBATCH*169)             // 2028 scalar threads (scale 3)
#define DEC_TOTAL (QEND + S3THREADS)         // 42604

// Scratch (__device__ globals — zero-initialized at load; nms re-zeroes g_cnt after use)
__device__ int   g_cnt[NBATCH*80];
__device__ float g_bucket[NBATCH*80*CAP*8];  // b0,b1,b2,b3 | area,conf,idx,pad

__constant__ float c_anch[3][3][2] = {
  {{10.f,13.f},{16.f,30.f},{33.f,23.f}},
  {{30.f,61.f},{62.f,45.f},{59.f,119.f}},
  {{116.f,90.f},{156.f,198.f},{373.f,326.f}}
};

__device__ __forceinline__ float sigmoidf_(float x){ return 1.0f/(1.0f + expf(-x)); }
__device__ __forceinline__ float getc(float4 v, int k){
    return (k==0)?v.x : (k==1)?v.y : (k==2)?v.z : v.w;
}

// Decode. Phase A computes boxes and appends valid ones to the class buckets
// (the ONLY data NMS reads), then fence + programmatic trigger releases the
// dependent NMS grid. Phase B (scattered det/keep stores) overlaps with NMS.
// keep stores are disjoint: decode zeroes only non-bucket boxes; NMS writes
// keep for every bucket entry.
__global__ void decode_kernel(const float* __restrict__ f1,
                              const float* __restrict__ f2,
                              const float* __restrict__ f3,
                              float* __restrict__ det_out,
                              float* __restrict__ keep_out){
    int T = blockIdx.x*blockDim.x + threadIdx.x;

    bool valid = false, zero_keep = false, did_bucket = false;
    float ob0=0, ob1=0, ob2=0, ob3=0, oconf=0; int obi=0; long oo=0;

    if (T < QEND){
        // Hybrid quad path (scales 1,2): team of 4 lanes per spatial quad,
        // float4 loads, exact first-occurrence argmax via (value, index) merge.
        int team = T >> 2;
        int sub  = T & 3;
        valid = (team < NQT);
        if (team >= NQT) team = NQT - 1;         // clamp; keep full warps for shfl

        int a = team / (NBATCH*QTOT);
        int r = team - a*(NBATCH*QTOT);
        int b = r / QTOT;
        int q = r - b*QTOT;
        const float* feat; int W; float stride; int nbase; int HW; int si; int s4;
        if (q < 676){ feat=f1; W=52; stride=8.0f;  nbase=0;    HW=2704; si=0; s4=q*4; }
        else        { feat=f2; W=26; stride=16.0f; nbase=8112; HW=676;  si=1; s4=(q-676)*4; }

        const float* fc = feat + ((long)b*255 + a*85)*HW + s4;

        const float* fcls = fc + 5L*HW;
        float4 best = *(const float4*)(fcls + (long)sub*HW);
        int bi0=sub, bi1=sub, bi2=sub, bi3=sub;
        #pragma unroll 5
        for (int i = 1; i < 20; i++){
            int e = sub + 4*i;
            float4 v = *(const float4*)(fcls + (long)e*HW);
            if (v.x > best.x){ best.x = v.x; bi0 = e; }
            if (v.y > best.y){ best.y = v.y; bi1 = e; }
            if (v.z > best.z){ best.z = v.z; bi2 = e; }
            if (v.w > best.w){ best.w = v.w; bi3 = e; }
        }
        #pragma unroll
        for (int off = 1; off < 4; off <<= 1){
            float ox = __shfl_xor_sync(0xFFFFFFFFu, best.x, off);
            float oy = __shfl_xor_sync(0xFFFFFFFFu, best.y, off);
            float oz = __shfl_xor_sync(0xFFFFFFFFu, best.z, off);
            float ow = __shfl_xor_sync(0xFFFFFFFFu, best.w, off);
            int o0 = __shfl_xor_sync(0xFFFFFFFFu, bi0, off);
            int o1 = __shfl_xor_sync(0xFFFFFFFFu, bi1, off);
            int o2 = __shfl_xor_sync(0xFFFFFFFFu, bi2, off);
            int o3 = __shfl_xor_sync(0xFFFFFFFFu, bi3, off);
            if (ox > best.x || (ox == best.x && o0 < bi0)){ best.x = ox; bi0 = o0; }
            if (oy > best.y || (oy == best.y && o1 < bi1)){ best.y = oy; bi1 = o1; }
            if (oz > best.z || (oz == best.z && o2 < bi2)){ best.z = oz; bi2 = o2; }
            if (ow > best.w || (ow == best.w && o3 < bi3)){ best.w = ow; bi3 = o3; }
        }
        int bi = (sub==0)?bi0 : (sub==1)?bi1 : (sub==2)?bi2 : bi3;

        float4 va  = *(const float4*)(fc + (long)sub*HW);
        float4 vc4 = *(const float4*)(fc + 4L*HW);
        int lbase = (threadIdx.x & 31) & ~3;
        float4 r0, r1, r2, r3;
        r0.x=__shfl_sync(0xFFFFFFFFu, va.x, lbase+0); r0.y=__shfl_sync(0xFFFFFFFFu, va.y, lbase+0);
        r0.z=__shfl_sync(0xFFFFFFFFu, va.z, lbase+0); r0.w=__shfl_sync(0xFFFFFFFFu, va.w, lbase+0);
        r1.x=__shfl_sync(0xFFFFFFFFu, va.x, lbase+1); r1.y=__shfl_sync(0xFFFFFFFFu, va.y, lbase+1);
        r1.z=__shfl_sync(0xFFFFFFFFu, va.z, lbase+1); r1.w=__shfl_sync(0xFFFFFFFFu, va.w, lbase+1);
        r2.x=__shfl_sync(0xFFFFFFFFu, va.x, lbase+2); r2.y=__shfl_sync(0xFFFFFFFFu, va.y, lbase+2);
        r2.z=__shfl_sync(0xFFFFFFFFu, va.z, lbase+2); r2.w=__shfl_sync(0xFFFFFFFFu, va.w, lbase+2);
        r3.x=__shfl_sync(0xFFFFFFFFu, va.x, lbase+3); r3.y=__shfl_sync(0xFFFFFFFFu, va.y, lbase+3);
        r3.z=__shfl_sync(0xFFFFFFFFu, va.z, lbase+3); r3.w=__shfl_sync(0xFFFFFFFFu, va.w, lbase+3);
        float tx = getc(r0, sub);
        float ty = getc(r1, sub);
        float tw = getc(r2, sub);
        float th = getc(r3, sub);
        float tc = getc(vc4, sub);

        // Reference math, same op order
        int s = s4 + sub;
        int h = s / W, w = s - h*W;
        float x  = (sigmoidf_(tx) + (float)w) * stride;
        float y  = (sigmoidf_(ty) + (float)h) * stride;
        float bw = expf(tw) * c_anch[si][a][0] * stride;
        float bh = expf(th) * c_anch[si][a][1] * stride;
        float conf = sigmoidf_(tc);
        float b0 = x - bw*0.5f, b1 = x + bw*0.5f;   // both from x (reference quirk)
        float b2 = y - bh*0.5f, b3 = y + bh*0.5f;   // both from y
        float area = fmaxf(b2-b0+1.0f, 0.0f) * fmaxf(b3-b1+1.0f, 0.0f);

        int n = nbase + (w*W + h)*3 + a;            // reference flatten order
        oo = (long)b*NBOX + n;
        ob0=b0; ob1=b1; ob2=b2; ob3=b3; oconf=conf; obi=bi;

        if (valid){
            if (conf > 0.5f){
                int bc_ = b*80 + bi;
                int pos = atomicAdd(&g_cnt[bc_], 1);
                if (pos < CAP){
                    float4* rec = (float4*)(g_bucket + ((long)bc_*CAP + pos)*8);
                    rec[0] = make_float4(b0, b1, b2, b3);
                    rec[1] = make_float4(area, conf, (float)n, 0.0f);
                    did_bucket = true;
                } else zero_keep = true;             // overflow: NMS won't write it
            } else zero_keep = true;                 // invalid: NMS won't write it
        }
    }
    else if (T < DEC_TOTAL){
        // Scalar path (scale 3, HW=169 odd). One thread per box.
        int idx = T - QEND;
        int a = idx / (NBATCH*169);
        int r = idx - a*(NBATCH*169);
        int b = r / 169;
        int s = r - b*169;
        const float* fc = f3 + ((long)b*255 + a*85)*169 + s;
        float tx = fc[0], ty = fc[169], tw = fc[338], th = fc[507], tc = fc[676];
        const float* fcls = fc + 5*169;
        float best = fcls[0]; int bi = 0;
        #pragma unroll 8
        for (int e = 1; e < 80; e++){
            float v = fcls[e*169];
            if (v > best){ best = v; bi = e; }
        }
        int h = s / 13, w = s - h*13;
        float x  = (sigmoidf_(tx) + (float)w) * 32.0f;
        float y  = (sigmoidf_(ty) + (float)h) * 32.0f;
        float bw = expf(tw) * c_anch[2][a][0] * 32.0f;
        float bh = expf(th) * c_anch[2][a][1] * 32.0f;
        float conf = sigmoidf_(tc);
        float b0 = x - bw*0.5f, b1 = x + bw*0.5f;
        float b2 = y - bh*0.5f, b3 = y + bh*0.5f;
        float area = fmaxf(b2-b0+1.0f, 0.0f) * fmaxf(b3-b1+1.0f, 0.0f);
        int n = 10140 + (w*13 + h)*3 + a;
        oo = (long)b*NBOX + n;
        ob0=b0; ob1=b1; ob2=b2; ob3=b3; oconf=conf; obi=bi;
        valid = true;
        if (conf > 0.5f){
            int bc_ = b*80 + bi;
            int pos = atomicAdd(&g_cnt[bc_], 1);
            if (pos < CAP){
                float4* rec = (float4*)(g_bucket + ((long)bc_*CAP + pos)*8);
                rec[0] = make_float4(b0, b1, b2, b3);
                rec[1] = make_float4(area, conf, (float)n, 0.0f);
                did_bucket = true;
            } else zero_keep = true;
        } else zero_keep = true;
    }

    // Release the dependent NMS grid: bucket data is complete and fenced.
    if (did_bucket) __threadfence();
    cudaTriggerProgrammaticLaunchCompletion();

    // Phase B: scattered output stores, overlapped with NMS execution.
    if (valid){
        float* dp = det_out + oo*6;
        dp[0]=ob0; dp[1]=ob1; dp[2]=ob2; dp[3]=ob3; dp[4]=oconf; dp[5]=(float)obi;
        if (zero_keep) keep_out[oo] = 0.0f;          // disjoint from NMS keep stores
    }
}

// NMS (R12 config — best measured): ONE block per bucket, 512 threads, PDL
// prelude fills sentinels before gridsync. keep written for EVERY bucket entry.
#define NMS_THREADS 512
__global__ void nms_kernel(float* __restrict__ keep_out){
    __shared__ float4 s_lo[CAP];     // b0,b1,b2,b3
    __shared__ float2 s_ac[CAP];     // area, conf
    __shared__ int    s_idx[CAP];

    int bc = blockIdx.x;                         // b*80 + c
    int b  = bc / 80;
    int t  = threadIdx.x;

    // ---- prelude: overlaps with decode under PDL ----
    for (int i = t; i < CAP; i += NMS_THREADS){
        s_lo[i] = make_float4(0.f,0.f,0.f,0.f);
        s_ac[i] = make_float2(0.f, -CUDART_INF_F);       // sentinel everywhere
    }
    __syncthreads();

    cudaGridDependencySynchronize();             // wait for decode's trigger

    int cnt = g_cnt[bc]; if (cnt > CAP) cnt = CAP;
    int cntPad = (cnt + 31) & ~31;

    const float4* base = (const float4*)(g_bucket + (long)bc*CAP*8);
    for (int i = t; i < cnt; i += NMS_THREADS){  // overwrite [0,cnt); pads stay sentinel
        float4 lo = base[2*i], hi = base[2*i+1];
        s_lo[i] = lo;
        s_ac[i] = make_float2(hi.x, hi.y);
        s_idx[i] = (int)hi.z;
    }
    __syncthreads();
    if (t == 0) g_cnt[bc] = 0;                   // restore zero for next call

    int warp = t >> 5, lane = t & 31;
    for (int i = warp; i < cnt; i += (NMS_THREADS/32)){
        float4 il = s_lo[i];                     // warp-uniform broadcast
        float2 ia = s_ac[i];
        bool found = false;
        for (int j0 = 0; j0 < cntPad; j0 += 32){
            int j = j0 + lane;                   // always in-bounds (padded)
            float4 jl = s_lo[j];                 // one LDS.128
            float2 ja = s_ac[j];                 // one LDS.64
            bool p = (ia.y < ja.y);              // conf_i < conf_j (false on pads & j==i)
            if (p){
                float wI = fminf(il.z, jl.z) - fmaxf(il.x, jl.x) + 1.0f;
                float hI = fminf(il.w, jl.w) - fmaxf(il.y, jl.y) + 1.0f;
                wI = fmaxf(wI, 0.0f); hI = fmaxf(hI, 0.0f);
                float inter = wI * hI;
                p = (inter > 0.0f) &&            // inter==0 -> ref iou 0 or NaN -> false
                    (inter / (ia.x + ja.x - inter) > 0.4f);  // same op order, IEEE div
            }
            if (__any_sync(0xFFFFFFFFu, p)){ found = true; break; }
        }
        if (lane == 0)
            keep_out[(long)b*NBOX + s_idx[i]] = found ? 1.0f : 0.0f;
    }
}

extern "C" void kernel_launch(void* const* d_in, const int* in_sizes, int n_in,
                              void* d_out, int out_size){
    const float* f1 = (const float*)d_in[0];   // (4,255,52,52)
    const float* f2 = (const float*)d_in[1];   // (4,255,26,26)
    const float* f3 = (const float*)d_in[2];   // (4,255,13,13)
    float* det  = (float*)d_out;               // (4,10647,6) then keep (4,10647)
    float* keep = det + DET_ELEMS;

    decode_kernel<<<(DEC_TOTAL + 127)/128, 128>>>(f1, f2, f3, det, keep);

    // NMS with programmatic dependent launch: launch+prelude overlap decode;
    // decode's early trigger releases gridsync before its det/keep store tail.
    cudaLaunchConfig_t cfg = {};
    cfg.gridDim  = dim3(NBATCH*80, 1, 1);
    cfg.blockDim = dim3(NMS_THREADS, 1, 1);
    cfg.dynamicSmemBytes = 0;
    cfg.stream = 0;
    cudaLaunchAttribute attr[1];
    attr[0].id = cudaLaunchAttributeProgrammaticStreamSerialization;
    attr[0].val.programmaticStreamSerializationAllowed = 1;
    cfg.attrs = attr;
    cfg.numAttrs = 1;
    cudaLaunchKernelEx(&cfg, nms_kernel, keep);
}

// round 15
// speedup vs baseline: 1.0755x; 1.0755x over previous
#include <cuda_runtime.h>
#include <math_constants.h>

#define NBOX   10647          // 52*52*3 + 26*26*3 + 13*13*3
#define NBATCH 4
#define DET_ELEMS (NBATCH*NBOX*6)
#define KEEP_ELEMS (NBATCH*NBOX)             // 42588 = 4*10647
#define CAP    256            // per-(batch,class) bucket capacity (mean ~66, >20 sigma safe)

#define QTOT    845           // float4-quads over scale1+scale2 spatial (676 + 169)
#define NQT     (3*NBATCH*QTOT)              // 10140 quad-teams
#define QTHREADS (NQT*4)                     // 40560 quad lanes
#define QEND    (((QTHREADS)+31) & ~31)      // 40576: pad to warp boundary
#define S3THREADS (3*NBATCH*169)             // 2028 scalar threads (scale 3)
#define DEC_TOTAL (QEND + S3THREADS)         // 42604

// Scratch (__device__ globals — zero-initialized at load; nms re-zeroes g_cnt after use)
__device__ int   g_cnt[NBATCH*80];
__device__ float g_bucket[NBATCH*80*CAP*8];  // b0,b1,b2,b3 | area,conf,idx,pad

__constant__ float c_anch[3][3][2] = {
  {{10.f,13.f},{16.f,30.f},{33.f,23.f}},
  {{30.f,61.f},{62.f,45.f},{59.f,119.f}},
  {{116.f,90.f},{156.f,198.f},{373.f,326.f}}
};

__device__ __forceinline__ float sigmoidf_(float x){ return 1.0f/(1.0f + expf(-x)); }
__device__ __forceinline__ float getc(float4 v, int k){
    return (k==0)?v.x : (k==1)?v.y : (k==2)?v.z : v.w;
}

// Full per-box epilogue: reference math (same op order), det stores (3x STG.64),
// bucket append. keep zeroing handled separately (coalesced float4 memset).
__device__ __forceinline__ void emit_box(
    float tx, float ty, float tw, float th, float tc,
    int s, int W, float stride, int si, int a, int b, int bi, int nbase,
    float* __restrict__ det_out)
{
    int h = s / W, w = s - h*W;
    float x  = (sigmoidf_(tx) + (float)w) * stride;
    float y  = (sigmoidf_(ty) + (float)h) * stride;
    float bw = expf(tw) * c_anch[si][a][0] * stride;
    float bh = expf(th) * c_anch[si][a][1] * stride;
    float conf = sigmoidf_(tc);

    float b0 = x - bw*0.5f, b1 = x + bw*0.5f;   // both from x (reference quirk)
    float b2 = y - bh*0.5f, b3 = y + bh*0.5f;   // both from y
    float area = fmaxf(b2-b0+1.0f, 0.0f) * fmaxf(b3-b1+1.0f, 0.0f);

    int n = nbase + (w*W + h)*3 + a;            // reference flatten order (W==H)
    long o = (long)b*NBOX + n;
    float2* dp2 = (float2*)(det_out + o*6);     // 24B*o is 8B-aligned
    dp2[0] = make_float2(b0, b1);
    dp2[1] = make_float2(b2, b3);
    dp2[2] = make_float2(conf, (float)bi);

    if (conf > 0.5f){
        int bc = b*80 + bi;
        int pos = atomicAdd(&g_cnt[bc], 1);
        if (pos < CAP){
            float4* rec = (float4*)(g_bucket + ((long)bc*CAP + pos)*8);
            rec[0] = make_float4(b0, b1, b2, b3);
            rec[1] = make_float4(area, conf, (float)n, 0.0f);
        }
    }
}

// Hybrid decode (R12, validated): team of 4 lanes per spatial quad; float4 loads,
// exact first-occurrence argmax via (value, smaller-index) merge. Additionally,
// threads T < KEEP_ELEMS/4 zero the keep array with coalesced float4 stores
// (NMS overwrites bucket entries after the kernel boundary).
__global__ void decode_kernel(const float* __restrict__ f1,
                              const float* __restrict__ f2,
                              const float* __restrict__ f3,
                              float* __restrict__ det_out,
                              float* __restrict__ keep_out){
    int T = blockIdx.x*blockDim.x + threadIdx.x;

    // Coalesced keep zeroing: 10647 float4 stores cover all 42588 entries.
    if (T < KEEP_ELEMS/4)
        ((float4*)keep_out)[T] = make_float4(0.f, 0.f, 0.f, 0.f);

    if (T < QEND){
        int team = T >> 2;
        int sub  = T & 3;
        bool valid = (team < NQT);
        if (team >= NQT) team = NQT - 1;         // clamp; keep full warps for shfl

        int a = team / (NBATCH*QTOT);
        int r = team - a*(NBATCH*QTOT);
        int b = r / QTOT;
        int q = r - b*QTOT;
        const float* feat; int W; float stride; int nbase; int HW; int si; int s4;
        if (q < 676){ feat=f1; W=52; stride=8.0f;  nbase=0;    HW=2704; si=0; s4=q*4; }
        else        { feat=f2; W=26; stride=16.0f; nbase=8112; HW=676;  si=1; s4=(q-676)*4; }

        const float* fc = feat + ((long)b*255 + a*85)*HW + s4;

        const float* fcls = fc + 5L*HW;
        float4 best = *(const float4*)(fcls + (long)sub*HW);
        int bi0=sub, bi1=sub, bi2=sub, bi3=sub;
        #pragma unroll 5
        for (int i = 1; i < 20; i++){
            int e = sub + 4*i;
            float4 v = *(const float4*)(fcls + (long)e*HW);
            if (v.x > best.x){ best.x = v.x; bi0 = e; }
            if (v.y > best.y){ best.y = v.y; bi1 = e; }
            if (v.z > best.z){ best.z = v.z; bi2 = e; }
            if (v.w > best.w){ best.w = v.w; bi3 = e; }
        }
        #pragma unroll
        for (int off = 1; off < 4; off <<= 1){
            float ox = __shfl_xor_sync(0xFFFFFFFFu, best.x, off);
            float oy = __shfl_xor_sync(0xFFFFFFFFu, best.y, off);
            float oz = __shfl_xor_sync(0xFFFFFFFFu, best.z, off);
            float ow = __shfl_xor_sync(0xFFFFFFFFu, best.w, off);
            int o0 = __shfl_xor_sync(0xFFFFFFFFu, bi0, off);
            int o1 = __shfl_xor_sync(0xFFFFFFFFu, bi1, off);
            int o2 = __shfl_xor_sync(0xFFFFFFFFu, bi2, off);
            int o3 = __shfl_xor_sync(0xFFFFFFFFu, bi3, off);
            if (ox > best.x || (ox == best.x && o0 < bi0)){ best.x = ox; bi0 = o0; }
            if (oy > best.y || (oy == best.y && o1 < bi1)){ best.y = oy; bi1 = o1; }
            if (oz > best.z || (oz == best.z && o2 < bi2)){ best.z = oz; bi2 = o2; }
            if (ow > best.w || (ow == best.w && o3 < bi3)){ best.w = ow; bi3 = o3; }
        }
        int bi = (sub==0)?bi0 : (sub==1)?bi1 : (sub==2)?bi2 : bi3;

        float4 va  = *(const float4*)(fc + (long)sub*HW);
        float4 vc4 = *(const float4*)(fc + 4L*HW);
        int lbase = (threadIdx.x & 31) & ~3;
        float4 r0, r1, r2, r3;
        r0.x=__shfl_sync(0xFFFFFFFFu, va.x, lbase+0); r0.y=__shfl_sync(0xFFFFFFFFu, va.y, lbase+0);
        r0.z=__shfl_sync(0xFFFFFFFFu, va.z, lbase+0); r0.w=__shfl_sync(0xFFFFFFFFu, va.w, lbase+0);
        r1.x=__shfl_sync(0xFFFFFFFFu, va.x, lbase+1); r1.y=__shfl_sync(0xFFFFFFFFu, va.y, lbase+1);
        r1.z=__shfl_sync(0xFFFFFFFFu, va.z, lbase+1); r1.w=__shfl_sync(0xFFFFFFFFu, va.w, lbase+1);
        r2.x=__shfl_sync(0xFFFFFFFFu, va.x, lbase+2); r2.y=__shfl_sync(0xFFFFFFFFu, va.y, lbase+2);
        r2.z=__shfl_sync(0xFFFFFFFFu, va.z, lbase+2); r2.w=__shfl_sync(0xFFFFFFFFu, va.w, lbase+2);
        r3.x=__shfl_sync(0xFFFFFFFFu, va.x, lbase+3); r3.y=__shfl_sync(0xFFFFFFFFu, va.y, lbase+3);
        r3.z=__shfl_sync(0xFFFFFFFFu, va.z, lbase+3); r3.w=__shfl_sync(0xFFFFFFFFu, va.w, lbase+3);
        float tx = getc(r0, sub);
        float ty = getc(r1, sub);
        float tw = getc(r2, sub);
        float th = getc(r3, sub);
        float tc = getc(vc4, sub);

        if (valid)
            emit_box(tx,ty,tw,th,tc, s4+sub, W, stride, si, a, b, bi, nbase, det_out);
    }
    else if (T < DEC_TOTAL){
        // Scalar path (scale 3, HW=169: odd -> no aligned float4). One thread per box.
        int idx = T - QEND;
        int a = idx / (NBATCH*169);
        int r = idx - a*(NBATCH*169);
        int b = r / 169;
        int s = r - b*169;
        const float* fc = f3 + ((long)b*255 + a*85)*169 + s;
        float tx = fc[0], ty = fc[169], tw = fc[338], th = fc[507], tc = fc[676];
        const float* fcls = fc + 5*169;
        float best = fcls[0]; int bi = 0;
        #pragma unroll 8
        for (int e = 1; e < 80; e++){
            float v = fcls[e*169];
            if (v > best){ best = v; bi = e; }
        }
        emit_box(tx,ty,tw,th,tc, s, 13, 32.0f, 2, a, b, bi, 10140, det_out);
    }
}

// NMS (R12 config — best measured): ONE block per bucket, 512 threads, PDL
// prelude fills sentinels before gridsync. keep written for every bucket entry.
#define NMS_THREADS 512
__global__ void nms_kernel(float* __restrict__ keep_out){
    __shared__ float4 s_lo[CAP];     // b0,b1,b2,b3
    __shared__ float2 s_ac[CAP];     // area, conf
    __shared__ int    s_idx[CAP];

    int bc = blockIdx.x;                         // b*80 + c
    int b  = bc / 80;
    int t  = threadIdx.x;

    // ---- prelude: overlaps with decode under PDL ----
    for (int i = t; i < CAP; i += NMS_THREADS){
        s_lo[i] = make_float4(0.f,0.f,0.f,0.f);
        s_ac[i] = make_float2(0.f, -CUDART_INF_F);       // sentinel everywhere
    }
    __syncthreads();

    cudaGridDependencySynchronize();             // wait for decode grid

    int cnt = g_cnt[bc]; if (cnt > CAP) cnt = CAP;
    int cntPad = (cnt + 31) & ~31;

    const float4* base = (const float4*)(g_bucket + (long)bc*CAP*8);
    for (int i = t; i < cnt; i += NMS_THREADS){  // overwrite [0,cnt); pads stay sentinel
        float4 lo = base[2*i], hi = base[2*i+1];
        s_lo[i] = lo;
        s_ac[i] = make_float2(hi.x, hi.y);
        s_idx[i] = (int)hi.z;
    }
    __syncthreads();
    if (t == 0) g_cnt[bc] = 0;                   // restore zero for next call

    int warp = t >> 5, lane = t & 31;
    for (int i = warp; i < cnt; i += (NMS_THREADS/32)){
        float4 il = s_lo[i];                     // warp-uniform broadcast
        float2 ia = s_ac[i];
        bool found = false;
        for (int j0 = 0; j0 < cntPad; j0 += 32){
            int j = j0 + lane;                   // always in-bounds (padded)
            float4 jl = s_lo[j];                 // one LDS.128
            float2 ja = s_ac[j];                 // one LDS.64
            bool p = (ia.y < ja.y);              // conf_i < conf_j (false on pads & j==i)
            if (p){
                float wI = fminf(il.z, jl.z) - fmaxf(il.x, jl.x) + 1.0f;
                float hI = fminf(il.w, jl.w) - fmaxf(il.y, jl.y) + 1.0f;
                wI = fmaxf(wI, 0.0f); hI = fmaxf(hI, 0.0f);
                float inter = wI * hI;
                p = (inter > 0.0f) &&            // inter==0 -> ref iou 0 or NaN -> false
                    (inter / (ia.x + ja.x - inter) > 0.4f);  // same op order, IEEE div
            }
            if (__any_sync(0xFFFFFFFFu, p)){ found = true; break; }
        }
        if (lane == 0)
            keep_out[(long)b*NBOX + s_idx[i]] = found ? 1.0f : 0.0f;
    }
}

extern "C" void kernel_launch(void* const* d_in, const int* in_sizes, int n_in,
                              void* d_out, int out_size){
    const float* f1 = (const float*)d_in[0];   // (4,255,52,52)
    const float* f2 = (const float*)d_in[1];   // (4,255,26,26)
    const float* f3 = (const float*)d_in[2];   // (4,255,13,13)
    float* det  = (float*)d_out;               // (4,10647,6) then keep (4,10647)
    float* keep = det + DET_ELEMS;

    decode_kernel<<<(DEC_TOTAL + 127)/128, 128>>>(f1, f2, f3, det, keep);

    // NMS with programmatic dependent launch: launch+prelude overlap decode.
    cudaLaunchConfig_t cfg = {};
    cfg.gridDim  = dim3(NBATCH*80, 1, 1);
    cfg.blockDim = dim3(NMS_THREADS, 1, 1);
    cfg.dynamicSmemBytes = 0;
    cfg.stream = 0;
    cudaLaunchAttribute attr[1];
    attr[0].id = cudaLaunchAttributeProgrammaticStreamSerialization;
    attr[0].val.programmaticStreamSerializationAllowed = 1;
    cfg.attrs = attr;
    cfg.numAttrs = 1;
    cudaLaunchKernelEx(&cfg, nms_kernel, keep);
}

// round 16
// speedup vs baseline: 1.1128x; 1.0347x over previous
#include <cuda_runtime.h>
#include <math_constants.h>

#define NBOX   10647          // 52*52*3 + 26*26*3 + 13*13*3
#define NBATCH 4
#define DET_ELEMS (NBATCH*NBOX*6)
#define KEEP_ELEMS (NBATCH*NBOX)             // 42588 = 4*10647
#define CAP    256            // per-(batch,class) bucket capacity (mean ~66, >20 sigma safe)
#define SPEC   96             // speculatively staged records (cnt <= 96 in practice)

#define QTOT    845           // float4-quads over scale1+scale2 spatial (676 + 169)
#define NQT     (3*NBATCH*QTOT)              // 10140 quad-teams
#define QTHREADS (NQT*4)                     // 40560 quad lanes
#define QEND    (((QTHREADS)+31) & ~31)      // 40576: pad to warp boundary
#define S3THREADS (3*NBATCH*169)             // 2028 scalar threads (scale 3)
#define DEC_TOTAL (QEND + S3THREADS)         // 42604

// Scratch (__device__ globals — zero-initialized at load; nms re-zeroes g_cnt after use)
__device__ int   g_cnt[NBATCH*80];
__device__ float g_bucket[NBATCH*80*CAP*8];  // b0,b1,b2,b3 | area,conf,idx,pad

__constant__ float c_anch[3][3][2] = {
  {{10.f,13.f},{16.f,30.f},{33.f,23.f}},
  {{30.f,61.f},{62.f,45.f},{59.f,119.f}},
  {{116.f,90.f},{156.f,198.f},{373.f,326.f}}
};

__device__ __forceinline__ float sigmoidf_(float x){ return 1.0f/(1.0f + expf(-x)); }
__device__ __forceinline__ float getc(float4 v, int k){
    return (k==0)?v.x : (k==1)?v.y : (k==2)?v.z : v.w;
}

// Full per-box epilogue: reference math (same op order), det stores (3x STG.64),
// bucket append. keep zeroing handled separately (coalesced float4 memset).
__device__ __forceinline__ void emit_box(
    float tx, float ty, float tw, float th, float tc,
    int s, int W, float stride, int si, int a, int b, int bi, int nbase,
    float* __restrict__ det_out)
{
    int h = s / W, w = s - h*W;
    float x  = (sigmoidf_(tx) + (float)w) * stride;
    float y  = (sigmoidf_(ty) + (float)h) * stride;
    float bw = expf(tw) * c_anch[si][a][0] * stride;
    float bh = expf(th) * c_anch[si][a][1] * stride;
    float conf = sigmoidf_(tc);

    float b0 = x - bw*0.5f, b1 = x + bw*0.5f;   // both from x (reference quirk)
    float b2 = y - bh*0.5f, b3 = y + bh*0.5f;   // both from y
    float area = fmaxf(b2-b0+1.0f, 0.0f) * fmaxf(b3-b1+1.0f, 0.0f);

    int n = nbase + (w*W + h)*3 + a;            // reference flatten order (W==H)
    long o = (long)b*NBOX + n;
    float2* dp2 = (float2*)(det_out + o*6);     // 24B*o is 8B-aligned
    dp2[0] = make_float2(b0, b1);
    dp2[1] = make_float2(b2, b3);
    dp2[2] = make_float2(conf, (float)bi);

    if (conf > 0.5f){
        int bc = b*80 + bi;
        int pos = atomicAdd(&g_cnt[bc], 1);
        if (pos < CAP){
            float4* rec = (float4*)(g_bucket + ((long)bc*CAP + pos)*8);
            rec[0] = make_float4(b0, b1, b2, b3);
            rec[1] = make_float4(area, conf, (float)n, 0.0f);
        }
    }
}

// Hybrid decode (R12, validated): team of 4 lanes per spatial quad; float4 loads,
// exact first-occurrence argmax via (value, smaller-index) merge. Threads
// T < KEEP_ELEMS/4 also zero the keep array with coalesced float4 stores
// (NMS overwrites bucket entries after the kernel boundary).
__global__ void decode_kernel(const float* __restrict__ f1,
                              const float* __restrict__ f2,
                              const float* __restrict__ f3,
                              float* __restrict__ det_out,
                              float* __restrict__ keep_out){
    int T = blockIdx.x*blockDim.x + threadIdx.x;

    if (T < KEEP_ELEMS/4)
        ((float4*)keep_out)[T] = make_float4(0.f, 0.f, 0.f, 0.f);

    if (T < QEND){
        int team = T >> 2;
        int sub  = T & 3;
        bool valid = (team < NQT);
        if (team >= NQT) team = NQT - 1;         // clamp; keep full warps for shfl

        int a = team / (NBATCH*QTOT);
        int r = team - a*(NBATCH*QTOT);
        int b = r / QTOT;
        int q = r - b*QTOT;
        const float* feat; int W; float stride; int nbase; int HW; int si; int s4;
        if (q < 676){ feat=f1; W=52; stride=8.0f;  nbase=0;    HW=2704; si=0; s4=q*4; }
        else        { feat=f2; W=26; stride=16.0f; nbase=8112; HW=676;  si=1; s4=(q-676)*4; }

        const float* fc = feat + ((long)b*255 + a*85)*HW + s4;

        const float* fcls = fc + 5L*HW;
        float4 best = *(const float4*)(fcls + (long)sub*HW);
        int bi0=sub, bi1=sub, bi2=sub, bi3=sub;
        #pragma unroll 5
        for (int i = 1; i < 20; i++){
            int e = sub + 4*i;
            float4 v = *(const float4*)(fcls + (long)e*HW);
            if (v.x > best.x){ best.x = v.x; bi0 = e; }
            if (v.y > best.y){ best.y = v.y; bi1 = e; }
            if (v.z > best.z){ best.z = v.z; bi2 = e; }
            if (v.w > best.w){ best.w = v.w; bi3 = e; }
        }
        #pragma unroll
        for (int off = 1; off < 4; off <<= 1){
            float ox = __shfl_xor_sync(0xFFFFFFFFu, best.x, off);
            float oy = __shfl_xor_sync(0xFFFFFFFFu, best.y, off);
            float oz = __shfl_xor_sync(0xFFFFFFFFu, best.z, off);
            float ow = __shfl_xor_sync(0xFFFFFFFFu, best.w, off);
            int o0 = __shfl_xor_sync(0xFFFFFFFFu, bi0, off);
            int o1 = __shfl_xor_sync(0xFFFFFFFFu, bi1, off);
            int o2 = __shfl_xor_sync(0xFFFFFFFFu, bi2, off);
            int o3 = __shfl_xor_sync(0xFFFFFFFFu, bi3, off);
            if (ox > best.x || (ox == best.x && o0 < bi0)){ best.x = ox; bi0 = o0; }
            if (oy > best.y || (oy == best.y && o1 < bi1)){ best.y = oy; bi1 = o1; }
            if (oz > best.z || (oz == best.z && o2 < bi2)){ best.z = oz; bi2 = o2; }
            if (ow > best.w || (ow == best.w && o3 < bi3)){ best.w = ow; bi3 = o3; }
        }
        int bi = (sub==0)?bi0 : (sub==1)?bi1 : (sub==2)?bi2 : bi3;

        float4 va  = *(const float4*)(fc + (long)sub*HW);
        float4 vc4 = *(const float4*)(fc + 4L*HW);
        int lbase = (threadIdx.x & 31) & ~3;
        float4 r0, r1, r2, r3;
        r0.x=__shfl_sync(0xFFFFFFFFu, va.x, lbase+0); r0.y=__shfl_sync(0xFFFFFFFFu, va.y, lbase+0);
        r0.z=__shfl_sync(0xFFFFFFFFu, va.z, lbase+0); r0.w=__shfl_sync(0xFFFFFFFFu, va.w, lbase+0);
        r1.x=__shfl_sync(0xFFFFFFFFu, va.x, lbase+1); r1.y=__shfl_sync(0xFFFFFFFFu, va.y, lbase+1);
        r1.z=__shfl_sync(0xFFFFFFFFu, va.z, lbase+1); r1.w=__shfl_sync(0xFFFFFFFFu, va.w, lbase+1);
        r2.x=__shfl_sync(0xFFFFFFFFu, va.x, lbase+2); r2.y=__shfl_sync(0xFFFFFFFFu, va.y, lbase+2);
        r2.z=__shfl_sync(0xFFFFFFFFu, va.z, lbase+2); r2.w=__shfl_sync(0xFFFFFFFFu, va.w, lbase+2);
        r3.x=__shfl_sync(0xFFFFFFFFu, va.x, lbase+3); r3.y=__shfl_sync(0xFFFFFFFFu, va.y, lbase+3);
        r3.z=__shfl_sync(0xFFFFFFFFu, va.z, lbase+3); r3.w=__shfl_sync(0xFFFFFFFFu, va.w, lbase+3);
        float tx = getc(r0, sub);
        float ty = getc(r1, sub);
        float tw = getc(r2, sub);
        float th = getc(r3, sub);
        float tc = getc(vc4, sub);

        if (valid)
            emit_box(tx,ty,tw,th,tc, s4+sub, W, stride, si, a, b, bi, nbase, det_out);
    }
    else if (T < DEC_TOTAL){
        // Scalar path (scale 3, HW=169: odd -> no aligned float4). One thread per box.
        int idx = T - QEND;
        int a = idx / (NBATCH*169);
        int r = idx - a*(NBATCH*169);
        int b = r / 169;
        int s = r - b*169;
        const float* fc = f3 + ((long)b*255 + a*85)*169 + s;
        float tx = fc[0], ty = fc[169], tw = fc[338], th = fc[507], tc = fc[676];
        const float* fcls = fc + 5*169;
        float best = fcls[0]; int bi = 0;
        #pragma unroll 8
        for (int e = 1; e < 80; e++){
            float v = fcls[e*169];
            if (v > best){ best = v; bi = e; }
        }
        emit_box(tx,ty,tw,th,tc, s, 13, 32.0f, 2, a, b, bi, 10140, det_out);
    }
}

// NMS (R12 config + speculative staging): ONE block per bucket, 512 threads, PDL.
// After gridsync, the g_cnt load and the SPEC record loads issue CONCURRENTLY
// (loads don't depend on cnt; only the smem select does) — one global round-trip
// on the critical path instead of two. Slots >= cnt are discarded by the select.
#define NMS_THREADS 512
__global__ void nms_kernel(float* __restrict__ keep_out){
    __shared__ float4 s_lo[CAP];     // b0,b1,b2,b3
    __shared__ float2 s_ac[CAP];     // area, conf
    __shared__ int    s_idx[CAP];

    int bc = blockIdx.x;                         // b*80 + c
    int b  = bc / 80;
    int t  = threadIdx.x;

    // ---- prelude: overlaps with decode under PDL ----
    for (int i = t; i < CAP; i += NMS_THREADS){
        s_lo[i] = make_float4(0.f,0.f,0.f,0.f);
        s_ac[i] = make_float2(0.f, -CUDART_INF_F);       // sentinel everywhere
    }
    __syncthreads();

    cudaGridDependencySynchronize();             // wait for decode grid

    const float4* base = (const float4*)(g_bucket + (long)bc*CAP*8);

    // Issue cnt load and speculative record loads back-to-back (independent).
    int cnt = g_cnt[bc];
    float4 splo, sphi;
    if (t < SPEC){                               // threads 0..95 each fetch one record
        splo = base[2*t];
        sphi = base[2*t+1];
    }
    if (cnt > CAP) cnt = CAP;
    int cntPad = (cnt + 31) & ~31;

    if (t < SPEC && t < cnt){                    // select: real record or keep sentinel
        s_lo[t] = splo;
        s_ac[t] = make_float2(sphi.x, sphi.y);
        s_idx[t] = (int)sphi.z;
    }
    for (int i = SPEC + t; i < cnt; i += NMS_THREADS){   // tail (statistically never)
        float4 lo = base[2*i], hi = base[2*i+1];
        s_lo[i] = lo;
        s_ac[i] = make_float2(hi.x, hi.y);
        s_idx[i] = (int)hi.z;
    }
    __syncthreads();
    if (t == 0) g_cnt[bc] = 0;                   // restore zero for next call

    int warp = t >> 5, lane = t & 31;
    for (int i = warp; i < cnt; i += (NMS_THREADS/32)){
        float4 il = s_lo[i];                     // warp-uniform broadcast
        float2 ia = s_ac[i];
        bool found = false;
        for (int j0 = 0; j0 < cntPad; j0 += 32){
            int j = j0 + lane;                   // always in-bounds (padded)
            float4 jl = s_lo[j];                 // one LDS.128
            float2 ja = s_ac[j];                 // one LDS.64
            bool p = (ia.y < ja.y);              // conf_i < conf_j (false on pads & j==i)
            if (p){
                float wI = fminf(il.z, jl.z) - fmaxf(il.x, jl.x) + 1.0f;
                float hI = fminf(il.w, jl.w) - fmaxf(il.y, jl.y) + 1.0f;
                wI = fmaxf(wI, 0.0f); hI = fmaxf(hI, 0.0f);
                float inter = wI * hI;
                p = (inter > 0.0f) &&            // inter==0 -> ref iou 0 or NaN -> false
                    (inter / (ia.x + ja.x - inter) > 0.4f);  // same op order, IEEE div
            }
            if (__any_sync(0xFFFFFFFFu, p)){ found = true; break; }
        }
        if (lane == 0)
            keep_out[(long)b*NBOX + s_idx[i]] = found ? 1.0f : 0.0f;
    }
}

extern "C" void kernel_launch(void* const* d_in, const int* in_sizes, int n_in,
                              void* d_out, int out_size){
    const float* f1 = (const float*)d_in[0];   // (4,255,52,52)
    const float* f2 = (const float*)d_in[1];   // (4,255,26,26)
    const float* f3 = (const float*)d_in[2];   // (4,255,13,13)
    float* det  = (float*)d_out;               // (4,10647,6) then keep (4,10647)
    float* keep = det + DET_ELEMS;

    decode_kernel<<<(DEC_TOTAL + 127)/128, 128>>>(f1, f2, f3, det, keep);

    // NMS with programmatic dependent launch: launch+prelude overlap decode.
    cudaLaunchConfig_t cfg = {};
    cfg.gridDim  = dim3(NBATCH*80, 1, 1);
    cfg.blockDim = dim3(NMS_THREADS, 1, 1);
    cfg.dynamicSmemBytes = 0;
    cfg.stream = 0;
    cudaLaunchAttribute attr[1];
    attr[0].id = cudaLaunchAttributeProgrammaticStreamSerialization;
    attr[0].val.programmaticStreamSerializationAllowed = 1;
    cfg.attrs = attr;
    cfg.numAttrs = 1;
    cudaLaunchKernelEx(&cfg, nms_kernel, keep);
}